// round 13
// baseline (speedup 1.0000x reference)
#include <cuda_runtime.h>
#include <cuda_bf16.h>
#include <math.h>
#include <stdint.h>

#define N_NODES 50000
#define N_EDGES 800000
#define HH 256
#define NHEADS 4
#define MPAD 50048
#define NBLK 196          // ceil(N_NODES/256)

// ---------------- scratch ----------------
__device__ float g_h  [(size_t)N_NODES * HH];
__device__ float g_el [N_NODES * NHEADS];
__device__ float g_er [N_NODES * NHEADS];
__device__ int   g_rowptr[N_NODES + 1];
__device__ int   g_counts[N_NODES];
__device__ int   g_csr_src[N_EDGES];
__device__ int   g_part[NBLK];
__device__ int   g_partoff[NBLK];
// A operand for layers 1-2 in mma A-FRAGMENT order (tiles of 16x16; tail rows stay zero)
__device__ __nv_bfloat16 g_a_hi[(size_t)MPAD * 256];
__device__ __nv_bfloat16 g_a_lo[(size_t)MPAD * 256];
// weights in mma B-FRAGMENT order
__device__ __nv_bfloat16 g_w_hi[3 * 256 * 256];
__device__ __nv_bfloat16 g_w_lo[3 * 256 * 256];

// ---------------- weight conversion to fragment layout (+ count zeroing) ----------------
__global__ void convert_w_all_k(const float* __restrict__ W0,
                                const float* __restrict__ W1,
                                const float* __restrict__ W2) {
    int i = blockIdx.x * blockDim.x + threadIdx.x;
    if (i < N_NODES) g_counts[i] = 0;
    const float* W;
    __nv_bfloat16 *oh, *ol;
    int K, idx;
    if (i < 128 * 256) {
        W = W0; K = 128; idx = i;
        oh = g_w_hi + 0 * 65536; ol = g_w_lo + 0 * 65536;
    } else if (i < 128 * 256 + 256 * 256) {
        W = W1; K = 256; idx = i - 128 * 256;
        oh = g_w_hi + 1 * 65536; ol = g_w_lo + 1 * 65536;
    } else if (i < 128 * 256 + 2 * 256 * 256) {
        W = W2; K = 256; idx = i - 128 * 256 - 256 * 256;
        oh = g_w_hi + 2 * 65536; ol = g_w_lo + 2 * 65536;
    } else return;
    int k = idx / 256, n = idx % 256;        // W is [K][256] row-major
    float a = W[idx];
    __nv_bfloat16 hi = __float2bfloat16(a);
    __nv_bfloat16 lo = __float2bfloat16(a - __bfloat162float(hi));
    int nt = n >> 4, kt = k >> 4;
    int nn = n & 15, kq = k & 15;
    int m = ((kq >> 3) << 1) | (nn >> 3);
    int l = ((nn & 7) << 2) + ((kq & 7) >> 1);
    int off = (nt * (K >> 4) + kt) * 256 + l * 8 + m * 2 + (kq & 1);
    oh[off] = hi;
    ol[off] = lo;
}

// ---------------- CSR build ----------------
__global__ void hist_k(const int* __restrict__ dst, int E) {
    int i = blockIdx.x * blockDim.x + threadIdx.x;
    if (i < E) atomicAdd(&g_counts[dst[i]], 1);
}
__global__ void partial_k() {
    __shared__ int sh[256];
    int b = blockIdx.x, t = threadIdx.x;
    int i = b * 256 + t;
    sh[t] = (i < N_NODES) ? g_counts[i] : 0;
    __syncthreads();
#pragma unroll
    for (int off = 128; off >= 1; off >>= 1) {
        if (t < off) sh[t] += sh[t + off];
        __syncthreads();
    }
    if (t == 0) g_part[b] = sh[0];
}
__global__ void scanpart_k() {
    __shared__ int sh[256];
    int t = threadIdx.x;
    int v = (t < NBLK) ? g_part[t] : 0;
    sh[t] = v;
    __syncthreads();
#pragma unroll
    for (int off = 1; off < 256; off <<= 1) {
        int u = (t >= off) ? sh[t - off] : 0;
        __syncthreads();
        sh[t] += u;
        __syncthreads();
    }
    if (t < NBLK) g_partoff[t] = sh[t] - v;
    if (t == NBLK - 1) g_rowptr[N_NODES] = sh[t];
}
__global__ void rowptr_k() {
    __shared__ int sh[256];
    int b = blockIdx.x, t = threadIdx.x;
    int i = b * 256 + t;
    int v = (i < N_NODES) ? g_counts[i] : 0;
    sh[t] = v;
    __syncthreads();
#pragma unroll
    for (int off = 1; off < 256; off <<= 1) {
        int u = (t >= off) ? sh[t - off] : 0;
        __syncthreads();
        sh[t] += u;
        __syncthreads();
    }
    if (i < N_NODES) {
        g_rowptr[i] = g_partoff[b] + sh[t] - v;
        g_counts[i] = 0;
    }
}
__global__ void scatter_k(const int* __restrict__ src, const int* __restrict__ dst, int E) {
    int i = blockIdx.x * blockDim.x + threadIdx.x;
    if (i < E) {
        int d = dst[i];
        int pos = g_rowptr[d] + atomicAdd(&g_counts[d], 1);
        g_csr_src[pos] = src[i];
    }
}

// ---------------- warp-MMA helpers ----------------
__device__ __forceinline__ void ldsm4(uint32_t (&r)[4], uint32_t addr) {
    asm volatile("ldmatrix.sync.aligned.m8n8.x4.shared.b16 {%0,%1,%2,%3}, [%4];"
                 : "=r"(r[0]), "=r"(r[1]), "=r"(r[2]), "=r"(r[3]) : "r"(addr));
}
__device__ __forceinline__ void mma16816(float (&d)[4], const uint32_t (&a)[4],
                                         uint32_t b0, uint32_t b1) {
    asm volatile(
        "mma.sync.aligned.m16n8k16.row.col.f32.bf16.bf16.f32 "
        "{%0,%1,%2,%3}, {%4,%5,%6,%7}, {%8,%9}, {%0,%1,%2,%3};"
        : "+f"(d[0]), "+f"(d[1]), "+f"(d[2]), "+f"(d[3])
        : "r"(a[0]), "r"(a[1]), "r"(a[2]), "r"(a[3]), "r"(b0), "r"(b1));
}
__device__ __forceinline__ void mma16816v(float (&d)[4], const uint4& a,
                                          uint32_t b0, uint32_t b1) {
    asm volatile(
        "mma.sync.aligned.m16n8k16.row.col.f32.bf16.bf16.f32 "
        "{%0,%1,%2,%3}, {%4,%5,%6,%7}, {%8,%9}, {%0,%1,%2,%3};"
        : "+f"(d[0]), "+f"(d[1]), "+f"(d[2]), "+f"(d[3])
        : "r"(a.x), "r"(a.y), "r"(a.z), "r"(a.w), "r"(b0), "r"(b1));
}

#define LDA 80

// ===== epilogue: write C + fused el/er =====
__device__ __forceinline__ void gemm_epilogue(
    float (&acc)[2][8][4], float* __restrict__ C,
    const float* __restrict__ alw, const float* __restrict__ arw,
    int row0, int nbase, int warp_m, int warp_n, int lane)
{
    const int g = lane >> 2;
    const int tig = lane & 3;
    const int head = (nbase >> 6) + warp_n;
    const int cihb = tig * 2;
#pragma unroll
    for (int mt = 0; mt < 2; mt++) {
#pragma unroll
        for (int half = 0; half < 2; half++) {
            int grow = row0 + warp_m * 32 + mt * 16 + g + half * 8;
            if (grow >= N_NODES) continue;
            float sl = 0.f, sr = 0.f;
            float* cp = C + (size_t)grow * 256 + nbase + warp_n * 64;
#pragma unroll
            for (int nt = 0; nt < 8; nt++) {
                float c0 = acc[mt][nt][half * 2 + 0];
                float c1 = acc[mt][nt][half * 2 + 1];
                int cih = nt * 8 + cihb;
                *(float2*)(cp + cih) = make_float2(c0, c1);
                sl += c0 * alw[head * 64 + cih] + c1 * alw[head * 64 + cih + 1];
                sr += c0 * arw[head * 64 + cih] + c1 * arw[head * 64 + cih + 1];
            }
            sl += __shfl_xor_sync(0xffffffffu, sl, 1);
            sl += __shfl_xor_sync(0xffffffffu, sl, 2);
            sr += __shfl_xor_sync(0xffffffffu, sr, 1);
            sr += __shfl_xor_sync(0xffffffffu, sr, 2);
            if (tig == 0) {
                g_el[grow * 4 + head] = sl;
                g_er[grow * 4 + head] = sr;
            }
        }
    }
}

// ---------------- layer-0 GEMM (unchanged control): fp32 A staged, B direct-frag ----------------
template <int KT>
__device__ __forceinline__ void gemm_chunk_compute_bd(
    float (&acc)[2][8][4], uint32_t uAh, uint32_t uAl, uint32_t aOff,
    const __nv_bfloat16* __restrict__ BhW,
    const __nv_bfloat16* __restrict__ BlW,
    int kt0, int lane)
{
#pragma unroll
    for (int kk = 0; kk < 2; kk++) {
        const uint32_t kb = kk * 32;
        const int kt = kt0 + kk;
        uint32_t aH[2][4];
#pragma unroll
        for (int mt = 0; mt < 2; mt++) ldsm4(aH[mt], uAh + aOff + mt * 16 * LDA + kb);
        {
            uint4 bH[4];
#pragma unroll
            for (int p = 0; p < 4; p++)
                bH[p] = ((const uint4*)(BhW + (size_t)(p * KT + kt) * 256))[lane];
#pragma unroll
            for (int mt = 0; mt < 2; mt++)
#pragma unroll
                for (int p = 0; p < 4; p++) {
                    mma16816(acc[mt][2 * p + 0], aH[mt], bH[p].x, bH[p].z);
                    mma16816(acc[mt][2 * p + 1], aH[mt], bH[p].y, bH[p].w);
                }
            uint32_t aL[2][4];
#pragma unroll
            for (int mt = 0; mt < 2; mt++) ldsm4(aL[mt], uAl + aOff + mt * 16 * LDA + kb);
#pragma unroll
            for (int mt = 0; mt < 2; mt++)
#pragma unroll
                for (int p = 0; p < 4; p++) {
                    mma16816(acc[mt][2 * p + 0], aL[mt], bH[p].x, bH[p].z);
                    mma16816(acc[mt][2 * p + 1], aL[mt], bH[p].y, bH[p].w);
                }
        }
        {
            uint4 bL[4];
#pragma unroll
            for (int p = 0; p < 4; p++)
                bL[p] = ((const uint4*)(BlW + (size_t)(p * KT + kt) * 256))[lane];
#pragma unroll
            for (int mt = 0; mt < 2; mt++)
#pragma unroll
                for (int p = 0; p < 4; p++) {
                    mma16816(acc[mt][2 * p + 0], aH[mt], bL[p].x, bL[p].z);
                    mma16816(acc[mt][2 * p + 1], aH[mt], bL[p].y, bL[p].w);
                }
        }
    }
}

__global__ void __launch_bounds__(256, 2) gemm_l0_k(
    const float* __restrict__ Afp,
    const __nv_bfloat16* __restrict__ BhF, const __nv_bfloat16* __restrict__ BlF,
    float* __restrict__ C, const float* __restrict__ alw, const float* __restrict__ arw)
{
    constexpr int K = 128, KT = K / 16;
    __shared__ __align__(16) uint8_t sAh[128 * LDA];
    __shared__ __align__(16) uint8_t sAl[128 * LDA];

    const int t = threadIdx.x;
    const int wid = t >> 5, lane = t & 31;
    const int warp_m = wid & 3, warp_n = wid >> 2;
    const int row0 = blockIdx.y * 128;
    const int nbase = blockIdx.x * 128;

    float acc[2][8][4];
#pragma unroll
    for (int i = 0; i < 2; i++)
#pragma unroll
        for (int j = 0; j < 8; j++)
#pragma unroll
            for (int q = 0; q < 4; q++) acc[i][j][q] = 0.f;

    const uint32_t uAh = (uint32_t)__cvta_generic_to_shared(sAh);
    const uint32_t uAl = (uint32_t)__cvta_generic_to_shared(sAl);
    const uint32_t rowOff = (uint32_t)(lane & 15) * LDA + (uint32_t)((lane >> 4) << 4);
    const uint32_t aOff = (uint32_t)warp_m * 32 * LDA + rowOff;
    const int ntb = (nbase >> 4) + warp_n * 4;
    const __nv_bfloat16* BhW = BhF + (size_t)ntb * KT * 256;
    const __nv_bfloat16* BlW = BlF + (size_t)ntb * KT * 256;

    const int lrow = t >> 1;
    const int lkq = (t & 1) * 16;
    const int arow = row0 + lrow;
    const bool aok = arow < N_NODES;

    for (int k0 = 0; k0 < K; k0 += 32) {
        {
            uint8_t* da = sAh + lrow * LDA + lkq * 2;
            uint8_t* dl = sAl + lrow * LDA + lkq * 2;
            const float* pa32 = Afp + (size_t)arow * K + k0 + lkq;
            float f[16];
#pragma unroll
            for (int q = 0; q < 4; q++) {
                float4 v = aok ? ((const float4*)pa32)[q] : make_float4(0.f, 0.f, 0.f, 0.f);
                f[q * 4 + 0] = v.x; f[q * 4 + 1] = v.y;
                f[q * 4 + 2] = v.z; f[q * 4 + 3] = v.w;
            }
            __nv_bfloat16 hi[16], lo[16];
#pragma unroll
            for (int q = 0; q < 16; q++) {
                hi[q] = __float2bfloat16(f[q]);
                lo[q] = __float2bfloat16(f[q] - __bfloat162float(hi[q]));
            }
            *(uint4*)(da +  0) = ((const uint4*)hi)[0];
            *(uint4*)(da + 16) = ((const uint4*)hi)[1];
            *(uint4*)(dl +  0) = ((const uint4*)lo)[0];
            *(uint4*)(dl + 16) = ((const uint4*)lo)[1];
        }
        __syncthreads();
        gemm_chunk_compute_bd<KT>(acc, uAh, uAl, aOff, BhW, BlW, k0 >> 4, lane);
        __syncthreads();
    }
    gemm_epilogue(acc, C, alw, arw, row0, nbase, warp_m, warp_n, lane);
}

// ---------------- layers 1-2 GEMM: A AND B direct-fragment; no smem, no barriers ----------------
__global__ void __launch_bounds__(256, 2) gemm_ff_k(
    const __nv_bfloat16* __restrict__ AhF, const __nv_bfloat16* __restrict__ AlF,
    const __nv_bfloat16* __restrict__ BhF, const __nv_bfloat16* __restrict__ BlF,
    float* __restrict__ C, const float* __restrict__ alw, const float* __restrict__ arw)
{
    constexpr int KT = 16;   // K = 256
    const int t = threadIdx.x;
    const int wid = t >> 5, lane = t & 31;
    const int warp_m = wid & 3, warp_n = wid >> 2;
    const int row0 = blockIdx.y * 128;
    const int nbase = blockIdx.x * 128;

    float acc[2][8][4];
#pragma unroll
    for (int i = 0; i < 2; i++)
#pragma unroll
        for (int j = 0; j < 8; j++)
#pragma unroll
            for (int q = 0; q < 4; q++) acc[i][j][q] = 0.f;

    const int rtile = (row0 + warp_m * 32) >> 4;   // A tiles rtile, rtile+1
    const uint4* Ah4 = (const uint4*)AhF;
    const uint4* Al4 = (const uint4*)AlF;
    const int ntb = (nbase >> 4) + warp_n * 4;
    const __nv_bfloat16* BhW = BhF + (size_t)ntb * KT * 256;
    const __nv_bfloat16* BlW = BlF + (size_t)ntb * KT * 256;

    for (int kt = 0; kt < KT; kt++) {
        uint4 aH[2], aL[2];
#pragma unroll
        for (int mt = 0; mt < 2; mt++) {
            size_t ti = ((size_t)(rtile + mt) * KT + kt) * 32 + lane;
            aH[mt] = Ah4[ti];
            aL[mt] = Al4[ti];
        }
        {
            uint4 bH[4];
#pragma unroll
            for (int p = 0; p < 4; p++)
                bH[p] = ((const uint4*)(BhW + (size_t)(p * KT + kt) * 256))[lane];
#pragma unroll
            for (int mt = 0; mt < 2; mt++)
#pragma unroll
                for (int p = 0; p < 4; p++) {
                    mma16816v(acc[mt][2 * p + 0], aH[mt], bH[p].x, bH[p].z);
                    mma16816v(acc[mt][2 * p + 1], aH[mt], bH[p].y, bH[p].w);
                }
#pragma unroll
            for (int mt = 0; mt < 2; mt++)
#pragma unroll
                for (int p = 0; p < 4; p++) {
                    mma16816v(acc[mt][2 * p + 0], aL[mt], bH[p].x, bH[p].z);
                    mma16816v(acc[mt][2 * p + 1], aL[mt], bH[p].y, bH[p].w);
                }
        }
        {
            uint4 bL[4];
#pragma unroll
            for (int p = 0; p < 4; p++)
                bL[p] = ((const uint4*)(BlW + (size_t)(p * KT + kt) * 256))[lane];
#pragma unroll
            for (int mt = 0; mt < 2; mt++)
#pragma unroll
                for (int p = 0; p < 4; p++) {
                    mma16816v(acc[mt][2 * p + 0], aH[mt], bL[p].x, bL[p].z);
                    mma16816v(acc[mt][2 * p + 1], aH[mt], bL[p].y, bL[p].w);
                }
        }
    }
    gemm_epilogue(acc, C, alw, arw, row0, nbase, warp_m, warp_n, lane);
}

// ---------------- single-pass aggregate; non-last layers emit A in fragment order ----------------
template <bool LAST>
__global__ void __launch_bounds__(128) aggregate_k(const float* __restrict__ h,
                                                   float* __restrict__ out,
                                                   const float* __restrict__ Wout,
                                                   const float* __restrict__ bout, int N) {
    int v = (blockIdx.x * 128 + threadIdx.x) >> 5;
    int lane = threadIdx.x & 31;
    if (v >= N) return;
    int hd = lane >> 3;

    float4 er4 = ((const float4*)g_er)[v];
    float erv = (hd == 0) ? er4.x : (hd == 1) ? er4.y : (hd == 2) ? er4.z : er4.w;

    int r0 = g_rowptr[v];
    int r1 = g_rowptr[v + 1];

    float ssum = 0.f;
    float4 acca = make_float4(0.f, 0.f, 0.f, 0.f);
    float4 accb = make_float4(0.f, 0.f, 0.f, 0.f);

    int j = r0;
    for (; j + 2 <= r1; j += 2) {
        int s0 = g_csr_src[j];
        int s1 = g_csr_src[j + 1];
        float4 el40 = ((const float4*)g_el)[s0];
        float4 el41 = ((const float4*)g_el)[s1];
        const float4* hp0 = (const float4*)(h + (size_t)s0 * HH + lane * 8);
        const float4* hp1 = (const float4*)(h + (size_t)s1 * HH + lane * 8);
        float4 ha0 = hp0[0], hb0 = hp0[1];
        float4 ha1 = hp1[0], hb1 = hp1[1];
        float e0 = ((hd == 0) ? el40.x : (hd == 1) ? el40.y : (hd == 2) ? el40.z : el40.w) + erv;
        float e1 = ((hd == 0) ? el41.x : (hd == 1) ? el41.y : (hd == 2) ? el41.z : el41.w) + erv;
        e0 = (e0 > 0.f) ? e0 : 0.2f * e0;
        e1 = (e1 > 0.f) ? e1 : 0.2f * e1;
        float w0 = __expf(e0);
        float w1 = __expf(e1);
        ssum += w0 + w1;
        acca.x = fmaf(w0, ha0.x, fmaf(w1, ha1.x, acca.x));
        acca.y = fmaf(w0, ha0.y, fmaf(w1, ha1.y, acca.y));
        acca.z = fmaf(w0, ha0.z, fmaf(w1, ha1.z, acca.z));
        acca.w = fmaf(w0, ha0.w, fmaf(w1, ha1.w, acca.w));
        accb.x = fmaf(w0, hb0.x, fmaf(w1, hb1.x, accb.x));
        accb.y = fmaf(w0, hb0.y, fmaf(w1, hb1.y, accb.y));
        accb.z = fmaf(w0, hb0.z, fmaf(w1, hb1.z, accb.z));
        accb.w = fmaf(w0, hb0.w, fmaf(w1, hb1.w, accb.w));
    }
    if (j < r1) {
        int s0 = g_csr_src[j];
        float4 el40 = ((const float4*)g_el)[s0];
        const float4* hp0 = (const float4*)(h + (size_t)s0 * HH + lane * 8);
        float4 ha0 = hp0[0], hb0 = hp0[1];
        float e0 = ((hd == 0) ? el40.x : (hd == 1) ? el40.y : (hd == 2) ? el40.z : el40.w) + erv;
        e0 = (e0 > 0.f) ? e0 : 0.2f * e0;
        float w0 = __expf(e0);
        ssum += w0;
        acca.x = fmaf(w0, ha0.x, acca.x);
        acca.y = fmaf(w0, ha0.y, acca.y);
        acca.z = fmaf(w0, ha0.z, acca.z);
        acca.w = fmaf(w0, ha0.w, acca.w);
        accb.x = fmaf(w0, hb0.x, accb.x);
        accb.y = fmaf(w0, hb0.y, accb.y);
        accb.z = fmaf(w0, hb0.z, accb.z);
        accb.w = fmaf(w0, hb0.w, accb.w);
    }

    float inv = 1.f / (ssum + 1e-9f);
    float o[8] = {acca.x * inv, acca.y * inv, acca.z * inv, acca.w * inv,
                  accb.x * inv, accb.y * inv, accb.z * inv, accb.w * inv};
#pragma unroll
    for (int i = 0; i < 8; i++) o[i] = (o[i] > 0.f) ? o[i] : expm1f(o[i]);

    if (LAST) {
        const int dbase = (lane & 7) * 8;
        float s = 0.f;
#pragma unroll
        for (int i = 0; i < 8; i++) s += o[i] * Wout[dbase + i];
#pragma unroll
        for (int off = 16; off >= 1; off >>= 1) s += __shfl_xor_sync(0xffffffffu, s, off);
        if (lane == 0) {
            float r = 0.25f * s + bout[0];
            out[v] = (r > 0.f) ? r : 0.f;
        }
    } else {
        // bf16 hi/lo split written directly in mma A-fragment order.
        // For row v, k = lane*8 + j:  tile = (v>>4)*16 + (lane>>1),
        //   uint32 idx within tile = (v&7)*16 + (j>>1)*4 + slot,
        //   slot = ((lane&1)<<1) | ((v>>3)&1).
        __nv_bfloat16 hi[8], lo[8];
#pragma unroll
        for (int i = 0; i < 8; i++) {
            hi[i] = __float2bfloat16(o[i]);
            lo[i] = __float2bfloat16(o[i] - __bfloat162float(hi[i]));
        }
        uint32_t* wh32 = (uint32_t*)g_a_hi;
        uint32_t* wl32 = (uint32_t*)g_a_lo;
        const uint32_t* hp32 = (const uint32_t*)hi;
        const uint32_t* lp32 = (const uint32_t*)lo;
        size_t tb = ((size_t)(v >> 4) * 16 + (lane >> 1)) * 128
                  + (size_t)(v & 7) * 16
                  + (((lane & 1) << 1) | ((v >> 3) & 1));
#pragma unroll
        for (int i = 0; i < 4; i++) {
            wh32[tb + i * 4] = hp32[i];
            wl32[tb + i * 4] = lp32[i];
        }
    }
}

// ---------------- launch ----------------
extern "C" void kernel_launch(void* const* d_in, const int* in_sizes, int n_in,
                              void* d_out, int out_size) {
    const float* x    = (const float*)d_in[0];
    const int*   src  = (const int*)d_in[1];
    const int*   dst  = (const int*)d_in[2];
    const float* W0   = (const float*)d_in[3];
    const float* al0  = (const float*)d_in[4];
    const float* ar0  = (const float*)d_in[5];
    const float* W1   = (const float*)d_in[6];
    const float* al1  = (const float*)d_in[7];
    const float* ar1  = (const float*)d_in[8];
    const float* W2   = (const float*)d_in[9];
    const float* al2  = (const float*)d_in[10];
    const float* ar2  = (const float*)d_in[11];
    const float* Wout = (const float*)d_in[12];
    const float* bout = (const float*)d_in[13];

    const int N = N_NODES;
    const int E = N_EDGES;

    float *h;
    __nv_bfloat16 *ah, *al, *wh, *wl;
    cudaGetSymbolAddress((void**)&h, g_h);
    cudaGetSymbolAddress((void**)&ah, g_a_hi);
    cudaGetSymbolAddress((void**)&al, g_a_lo);
    cudaGetSymbolAddress((void**)&wh, g_w_hi);
    cudaGetSymbolAddress((void**)&wl, g_w_lo);

    dim3 ggrid(2, (N + 127) / 128);
    const int warpGrid = (N + 3) / 4;
    const int wtotal = 128 * 256 + 2 * 256 * 256;

    convert_w_all_k<<<(wtotal + 255) / 256, 256>>>(W0, W1, W2);
    hist_k<<<(E + 255) / 256, 256>>>(dst, E);
    partial_k<<<NBLK, 256>>>();
    // slot 3 (profiled): layer-0 GEMM — unchanged control
    gemm_l0_k<<<ggrid, 256>>>(x, wh + 0 * 65536, wl + 0 * 65536, h, al0, ar0);
    scanpart_k<<<1, 256>>>();
    rowptr_k<<<NBLK, 256>>>();
    scatter_k<<<(E + 255) / 256, 256>>>(src, dst, E);
    aggregate_k<false><<<warpGrid, 128>>>(h, nullptr, nullptr, nullptr, N);
    gemm_ff_k<<<ggrid, 256>>>(ah, al, wh + 1 * 65536, wl + 1 * 65536, h, al1, ar1);
    aggregate_k<false><<<warpGrid, 128>>>(h, nullptr, nullptr, nullptr, N);
    gemm_ff_k<<<ggrid, 256>>>(ah, al, wh + 2 * 65536, wl + 2 * 65536, h, al2, ar2);
    aggregate_k<true><<<warpGrid, 128>>>(h, (float*)d_out, Wout, bout, N);
}

// round 14
// speedup vs baseline: 1.1141x; 1.1141x over previous
#include <cuda_runtime.h>
#include <cuda_bf16.h>
#include <math.h>
#include <stdint.h>

#define N_NODES 50000
#define N_EDGES 800000
#define HH 256
#define NHEADS 4
#define MPAD 50048
#define NBLK 196          // ceil(N_NODES/256)

// ---------------- scratch ----------------
__device__ float g_h  [(size_t)N_NODES * HH];
__device__ float g_el [N_NODES * NHEADS];
__device__ float g_er [N_NODES * NHEADS];
__device__ int   g_rowptr[N_NODES + 1];
__device__ int   g_counts[N_NODES];
__device__ int   g_csr_src[N_EDGES];
__device__ int   g_part[NBLK];
__device__ int   g_partoff[NBLK];
__device__ __nv_bfloat16 g_a_hi[(size_t)MPAD * 256];
__device__ __nv_bfloat16 g_a_lo[(size_t)MPAD * 256];
// weights in mma B-FRAGMENT order
__device__ __nv_bfloat16 g_w_hi[3 * 256 * 256];
__device__ __nv_bfloat16 g_w_lo[3 * 256 * 256];

// ---------------- weight conversion to fragment layout ----------------
__global__ void convert_w_all_k(const float* __restrict__ W0,
                                const float* __restrict__ W1,
                                const float* __restrict__ W2) {
    int i = blockIdx.x * blockDim.x + threadIdx.x;
    const float* W;
    __nv_bfloat16 *oh, *ol;
    int K, idx;
    if (i < 128 * 256) {
        W = W0; K = 128; idx = i;
        oh = g_w_hi + 0 * 65536; ol = g_w_lo + 0 * 65536;
    } else if (i < 128 * 256 + 256 * 256) {
        W = W1; K = 256; idx = i - 128 * 256;
        oh = g_w_hi + 1 * 65536; ol = g_w_lo + 1 * 65536;
    } else if (i < 128 * 256 + 2 * 256 * 256) {
        W = W2; K = 256; idx = i - 128 * 256 - 256 * 256;
        oh = g_w_hi + 2 * 65536; ol = g_w_lo + 2 * 65536;
    } else return;
    int k = idx / 256, n = idx % 256;        // W is [K][256] row-major
    float a = W[idx];
    __nv_bfloat16 hi = __float2bfloat16(a);
    __nv_bfloat16 lo = __float2bfloat16(a - __bfloat162float(hi));
    int nt = n >> 4, kt = k >> 4;
    int nn = n & 15, kq = k & 15;
    int m = ((kq >> 3) << 1) | (nn >> 3);
    int l = ((nn & 7) << 2) + ((kq & 7) >> 1);
    int off = (nt * (K >> 4) + kt) * 256 + l * 8 + m * 2 + (kq & 1);
    oh[off] = hi;
    ol[off] = lo;
}

// ---------------- CSR build ----------------
__global__ void zero_counts_k() {
    int i = blockIdx.x * blockDim.x + threadIdx.x;
    if (i < N_NODES) g_counts[i] = 0;
}
__global__ void hist_k(const int* __restrict__ dst, int E) {
    int i = blockIdx.x * blockDim.x + threadIdx.x;
    if (i < E) atomicAdd(&g_counts[dst[i]], 1);
}
__global__ void partial_k() {
    __shared__ int sh[256];
    int b = blockIdx.x, t = threadIdx.x;
    int i = b * 256 + t;
    sh[t] = (i < N_NODES) ? g_counts[i] : 0;
    __syncthreads();
#pragma unroll
    for (int off = 128; off >= 1; off >>= 1) {
        if (t < off) sh[t] += sh[t + off];
        __syncthreads();
    }
    if (t == 0) g_part[b] = sh[0];
}
__global__ void scanpart_k() {
    __shared__ int sh[256];
    int t = threadIdx.x;
    int v = (t < NBLK) ? g_part[t] : 0;
    sh[t] = v;
    __syncthreads();
#pragma unroll
    for (int off = 1; off < 256; off <<= 1) {
        int u = (t >= off) ? sh[t - off] : 0;
        __syncthreads();
        sh[t] += u;
        __syncthreads();
    }
    if (t < NBLK) g_partoff[t] = sh[t] - v;
    if (t == NBLK - 1) g_rowptr[N_NODES] = sh[t];
}
__global__ void rowptr_k() {
    __shared__ int sh[256];
    int b = blockIdx.x, t = threadIdx.x;
    int i = b * 256 + t;
    int v = (i < N_NODES) ? g_counts[i] : 0;
    sh[t] = v;
    __syncthreads();
#pragma unroll
    for (int off = 1; off < 256; off <<= 1) {
        int u = (t >= off) ? sh[t - off] : 0;
        __syncthreads();
        sh[t] += u;
        __syncthreads();
    }
    if (i < N_NODES) {
        g_rowptr[i] = g_partoff[b] + sh[t] - v;
        g_counts[i] = 0;
    }
}
__global__ void scatter_k(const int* __restrict__ src, const int* __restrict__ dst, int E) {
    int i = blockIdx.x * blockDim.x + threadIdx.x;
    if (i < E) {
        int d = dst[i];
        int pos = g_rowptr[d] + atomicAdd(&g_counts[d], 1);
        g_csr_src[pos] = src[i];
    }
}

// ---------------- warp-MMA helpers ----------------
__device__ __forceinline__ void ldsm4(uint32_t (&r)[4], uint32_t addr) {
    asm volatile("ldmatrix.sync.aligned.m8n8.x4.shared.b16 {%0,%1,%2,%3}, [%4];"
                 : "=r"(r[0]), "=r"(r[1]), "=r"(r[2]), "=r"(r[3]) : "r"(addr));
}
__device__ __forceinline__ void mma16816(float (&d)[4], const uint32_t (&a)[4],
                                         uint32_t b0, uint32_t b1) {
    asm volatile(
        "mma.sync.aligned.m16n8k16.row.col.f32.bf16.bf16.f32 "
        "{%0,%1,%2,%3}, {%4,%5,%6,%7}, {%8,%9}, {%0,%1,%2,%3};"
        : "+f"(d[0]), "+f"(d[1]), "+f"(d[2]), "+f"(d[3])
        : "r"(a[0]), "r"(a[1]), "r"(a[2]), "r"(a[3]), "r"(b0), "r"(b1));
}
__device__ __forceinline__ void cp16(uint32_t dst, const void* src, uint32_t n) {
    asm volatile("cp.async.cg.shared.global [%0], [%1], 16, %2;"
                 :: "r"(dst), "l"(src), "r"(n) : "memory");
}
#define CP_COMMIT() asm volatile("cp.async.commit_group;" ::: "memory")
#define CP_WAIT(n)  asm volatile("cp.async.wait_group %0;" :: "n"(n) : "memory")

#define LDA 80
#define ARR_BYTES (128 * LDA)
#define A_STAGE (2 * ARR_BYTES)
#define DB_SMEM (2 * A_STAGE)        // 40960

// ===== epilogue: write C + fused el/er =====
__device__ __forceinline__ void gemm_epilogue(
    float (&acc)[2][8][4], float* __restrict__ C,
    const float* __restrict__ alw, const float* __restrict__ arw,
    int row0, int nbase, int warp_m, int warp_n, int lane)
{
    const int g = lane >> 2;
    const int tig = lane & 3;
    const int head = (nbase >> 6) + warp_n;
    const int cihb = tig * 2;
#pragma unroll
    for (int mt = 0; mt < 2; mt++) {
#pragma unroll
        for (int half = 0; half < 2; half++) {
            int grow = row0 + warp_m * 32 + mt * 16 + g + half * 8;
            if (grow >= N_NODES) continue;
            float sl = 0.f, sr = 0.f;
            float* cp = C + (size_t)grow * 256 + nbase + warp_n * 64;
#pragma unroll
            for (int nt = 0; nt < 8; nt++) {
                float c0 = acc[mt][nt][half * 2 + 0];
                float c1 = acc[mt][nt][half * 2 + 1];
                int cih = nt * 8 + cihb;
                *(float2*)(cp + cih) = make_float2(c0, c1);
                sl += c0 * alw[head * 64 + cih] + c1 * alw[head * 64 + cih + 1];
                sr += c0 * arw[head * 64 + cih] + c1 * arw[head * 64 + cih + 1];
            }
            sl += __shfl_xor_sync(0xffffffffu, sl, 1);
            sl += __shfl_xor_sync(0xffffffffu, sl, 2);
            sr += __shfl_xor_sync(0xffffffffu, sr, 1);
            sr += __shfl_xor_sync(0xffffffffu, sr, 2);
            if (tig == 0) {
                g_el[grow * 4 + head] = sl;
                g_er[grow * 4 + head] = sr;
            }
        }
    }
}

// ===== compute one staged 32-K chunk; B fragments from global =====
template <int KT>
__device__ __forceinline__ void gemm_chunk_compute_bd(
    float (&acc)[2][8][4], uint32_t uAh, uint32_t uAl, uint32_t aOff,
    const __nv_bfloat16* __restrict__ BhW,
    const __nv_bfloat16* __restrict__ BlW,
    int kt0, int lane)
{
#pragma unroll
    for (int kk = 0; kk < 2; kk++) {
        const uint32_t kb = kk * 32;
        const int kt = kt0 + kk;
        uint32_t aH[2][4];
#pragma unroll
        for (int mt = 0; mt < 2; mt++) ldsm4(aH[mt], uAh + aOff + mt * 16 * LDA + kb);
        {
            uint4 bH[4];
#pragma unroll
            for (int p = 0; p < 4; p++)
                bH[p] = ((const uint4*)(BhW + (size_t)(p * KT + kt) * 256))[lane];
#pragma unroll
            for (int mt = 0; mt < 2; mt++)
#pragma unroll
                for (int p = 0; p < 4; p++) {
                    mma16816(acc[mt][2 * p + 0], aH[mt], bH[p].x, bH[p].z);
                    mma16816(acc[mt][2 * p + 1], aH[mt], bH[p].y, bH[p].w);
                }
            uint32_t aL[2][4];
#pragma unroll
            for (int mt = 0; mt < 2; mt++) ldsm4(aL[mt], uAl + aOff + mt * 16 * LDA + kb);
#pragma unroll
            for (int mt = 0; mt < 2; mt++)
#pragma unroll
                for (int p = 0; p < 4; p++) {
                    mma16816(acc[mt][2 * p + 0], aL[mt], bH[p].x, bH[p].z);
                    mma16816(acc[mt][2 * p + 1], aL[mt], bH[p].y, bH[p].w);
                }
        }
        {
            uint4 bL[4];
#pragma unroll
            for (int p = 0; p < 4; p++)
                bL[p] = ((const uint4*)(BlW + (size_t)(p * KT + kt) * 256))[lane];
#pragma unroll
            for (int mt = 0; mt < 2; mt++)
#pragma unroll
                for (int p = 0; p < 4; p++) {
                    mma16816(acc[mt][2 * p + 0], aH[mt], bL[p].x, bL[p].z);
                    mma16816(acc[mt][2 * p + 1], aH[mt], bL[p].y, bL[p].w);
                }
        }
    }
}

// ---------------- layer-0 GEMM: fp32 A staged + split, B direct-frag ----------------
__global__ void __launch_bounds__(256, 2) gemm_l0_k(
    const float* __restrict__ Afp,
    const __nv_bfloat16* __restrict__ BhF, const __nv_bfloat16* __restrict__ BlF,
    float* __restrict__ C, const float* __restrict__ alw, const float* __restrict__ arw)
{
    constexpr int K = 128, KT = K / 16;
    __shared__ __align__(16) uint8_t sAh[128 * LDA];
    __shared__ __align__(16) uint8_t sAl[128 * LDA];

    const int t = threadIdx.x;
    const int wid = t >> 5, lane = t & 31;
    const int warp_m = wid & 3, warp_n = wid >> 2;
    const int row0 = blockIdx.y * 128;
    const int nbase = blockIdx.x * 128;

    float acc[2][8][4];
#pragma unroll
    for (int i = 0; i < 2; i++)
#pragma unroll
        for (int j = 0; j < 8; j++)
#pragma unroll
            for (int q = 0; q < 4; q++) acc[i][j][q] = 0.f;

    const uint32_t uAh = (uint32_t)__cvta_generic_to_shared(sAh);
    const uint32_t uAl = (uint32_t)__cvta_generic_to_shared(sAl);
    const uint32_t rowOff = (uint32_t)(lane & 15) * LDA + (uint32_t)((lane >> 4) << 4);
    const uint32_t aOff = (uint32_t)warp_m * 32 * LDA + rowOff;
    const int ntb = (nbase >> 4) + warp_n * 4;
    const __nv_bfloat16* BhW = BhF + (size_t)ntb * KT * 256;
    const __nv_bfloat16* BlW = BlF + (size_t)ntb * KT * 256;

    const int lrow = t >> 1;
    const int lkq = (t & 1) * 16;
    const int arow = row0 + lrow;
    const bool aok = arow < N_NODES;

    for (int k0 = 0; k0 < K; k0 += 32) {
        {
            uint8_t* da = sAh + lrow * LDA + lkq * 2;
            uint8_t* dl = sAl + lrow * LDA + lkq * 2;
            const float* pa32 = Afp + (size_t)arow * K + k0 + lkq;
            float f[16];
#pragma unroll
            for (int q = 0; q < 4; q++) {
                float4 v = aok ? ((const float4*)pa32)[q] : make_float4(0.f, 0.f, 0.f, 0.f);
                f[q * 4 + 0] = v.x; f[q * 4 + 1] = v.y;
                f[q * 4 + 2] = v.z; f[q * 4 + 3] = v.w;
            }
            __nv_bfloat16 hi[16], lo[16];
#pragma unroll
            for (int q = 0; q < 16; q++) {
                hi[q] = __float2bfloat16(f[q]);
                lo[q] = __float2bfloat16(f[q] - __bfloat162float(hi[q]));
            }
            *(uint4*)(da +  0) = ((const uint4*)hi)[0];
            *(uint4*)(da + 16) = ((const uint4*)hi)[1];
            *(uint4*)(dl +  0) = ((const uint4*)lo)[0];
            *(uint4*)(dl + 16) = ((const uint4*)lo)[1];
        }
        __syncthreads();
        gemm_chunk_compute_bd<KT>(acc, uAh, uAl, aOff, BhW, BlW, k0 >> 4, lane);
        __syncthreads();
    }
    gemm_epilogue(acc, C, alw, arw, row0, nbase, warp_m, warp_n, lane);
}

// ---------------- layers 1-2 GEMM: bf16 A cp.async double buffer, B direct-frag ----------------
__global__ void __launch_bounds__(256, 2) gemm_db_k(
    const __nv_bfloat16* __restrict__ Ah, const __nv_bfloat16* __restrict__ Al,
    const __nv_bfloat16* __restrict__ BhF, const __nv_bfloat16* __restrict__ BlF,
    float* __restrict__ C, const float* __restrict__ alw, const float* __restrict__ arw)
{
    constexpr int K = 256, KT = K / 16;
    constexpr int NCHUNK = K / 32;
    extern __shared__ __align__(16) uint8_t smem[];

    const int t = threadIdx.x;
    const int wid = t >> 5, lane = t & 31;
    const int warp_m = wid & 3, warp_n = wid >> 2;
    const int row0 = blockIdx.y * 128;
    const int nbase = blockIdx.x * 128;

    float acc[2][8][4];
#pragma unroll
    for (int i = 0; i < 2; i++)
#pragma unroll
        for (int j = 0; j < 8; j++)
#pragma unroll
            for (int q = 0; q < 4; q++) acc[i][j][q] = 0.f;

    const uint32_t sbase = (uint32_t)__cvta_generic_to_shared(smem);
    const uint32_t rowOff = (uint32_t)(lane & 15) * LDA + (uint32_t)((lane >> 4) << 4);
    const uint32_t aOff = (uint32_t)warp_m * 32 * LDA + rowOff;
    const int ntb = (nbase >> 4) + warp_n * 4;
    const __nv_bfloat16* BhW = BhF + (size_t)ntb * KT * 256;
    const __nv_bfloat16* BlW = BlF + (size_t)ntb * KT * 256;

    const int lrow = t >> 1;
    const int lhalf = (t & 1) * 32;
    const int arow_real = row0 + lrow;
    const bool aok = arow_real < N_NODES;
    const int arow = aok ? arow_real : (N_NODES - 1);
    const uint32_t asz = aok ? 16u : 0u;
    const uint32_t dOff = (uint32_t)lrow * LDA + (uint32_t)lhalf;

    auto issue = [&](int c, int stage) {
        const int k0 = c * 32;
        const uint32_t sb = sbase + stage * A_STAGE + dOff;
        const char* pa = (const char*)(Ah + (size_t)arow * K + k0) + lhalf;
        const char* pl = (const char*)(Al + (size_t)arow * K + k0) + lhalf;
        cp16(sb + 0 * ARR_BYTES +  0, pa +  0, asz);
        cp16(sb + 0 * ARR_BYTES + 16, pa + 16, asz);
        cp16(sb + 1 * ARR_BYTES +  0, pl +  0, asz);
        cp16(sb + 1 * ARR_BYTES + 16, pl + 16, asz);
        CP_COMMIT();
    };

    issue(0, 0);
    for (int c = 0; c < NCHUNK; c++) {
        const int stage = c & 1;
        if (c + 1 < NCHUNK) {
            issue(c + 1, stage ^ 1);
            CP_WAIT(1);
        } else {
            CP_WAIT(0);
        }
        __syncthreads();
        const uint32_t uAh = sbase + stage * A_STAGE;
        gemm_chunk_compute_bd<KT>(acc, uAh, uAh + ARR_BYTES, aOff, BhW, BlW, c * 2, lane);
        __syncthreads();
    }
    gemm_epilogue(acc, C, alw, arw, row0, nbase, warp_m, warp_n, lane);
}

// ---------------- single-pass aggregate (R12 version) ----------------
template <bool LAST>
__global__ void __launch_bounds__(128) aggregate_k(const float* __restrict__ h,
                                                   float* __restrict__ out,
                                                   const float* __restrict__ Wout,
                                                   const float* __restrict__ bout, int N) {
    int v = (blockIdx.x * 128 + threadIdx.x) >> 5;
    int lane = threadIdx.x & 31;
    if (v >= N) return;
    int hd = lane >> 3;

    float4 er4 = ((const float4*)g_er)[v];
    float erv = (hd == 0) ? er4.x : (hd == 1) ? er4.y : (hd == 2) ? er4.z : er4.w;

    int r0 = g_rowptr[v];
    int r1 = g_rowptr[v + 1];

    float ssum = 0.f;
    float4 acca = make_float4(0.f, 0.f, 0.f, 0.f);
    float4 accb = make_float4(0.f, 0.f, 0.f, 0.f);

    int j = r0;
    for (; j + 2 <= r1; j += 2) {
        int s0 = g_csr_src[j];
        int s1 = g_csr_src[j + 1];
        float4 el40 = ((const float4*)g_el)[s0];
        float4 el41 = ((const float4*)g_el)[s1];
        const float4* hp0 = (const float4*)(h + (size_t)s0 * HH + lane * 8);
        const float4* hp1 = (const float4*)(h + (size_t)s1 * HH + lane * 8);
        float4 ha0 = hp0[0], hb0 = hp0[1];
        float4 ha1 = hp1[0], hb1 = hp1[1];
        float e0 = ((hd == 0) ? el40.x : (hd == 1) ? el40.y : (hd == 2) ? el40.z : el40.w) + erv;
        float e1 = ((hd == 0) ? el41.x : (hd == 1) ? el41.y : (hd == 2) ? el41.z : el41.w) + erv;
        e0 = (e0 > 0.f) ? e0 : 0.2f * e0;
        e1 = (e1 > 0.f) ? e1 : 0.2f * e1;
        float w0 = __expf(e0);
        float w1 = __expf(e1);
        ssum += w0 + w1;
        acca.x = fmaf(w0, ha0.x, fmaf(w1, ha1.x, acca.x));
        acca.y = fmaf(w0, ha0.y, fmaf(w1, ha1.y, acca.y));
        acca.z = fmaf(w0, ha0.z, fmaf(w1, ha1.z, acca.z));
        acca.w = fmaf(w0, ha0.w, fmaf(w1, ha1.w, acca.w));
        accb.x = fmaf(w0, hb0.x, fmaf(w1, hb1.x, accb.x));
        accb.y = fmaf(w0, hb0.y, fmaf(w1, hb1.y, accb.y));
        accb.z = fmaf(w0, hb0.z, fmaf(w1, hb1.z, accb.z));
        accb.w = fmaf(w0, hb0.w, fmaf(w1, hb1.w, accb.w));
    }
    if (j < r1) {
        int s0 = g_csr_src[j];
        float4 el40 = ((const float4*)g_el)[s0];
        const float4* hp0 = (const float4*)(h + (size_t)s0 * HH + lane * 8);
        float4 ha0 = hp0[0], hb0 = hp0[1];
        float e0 = ((hd == 0) ? el40.x : (hd == 1) ? el40.y : (hd == 2) ? el40.z : el40.w) + erv;
        e0 = (e0 > 0.f) ? e0 : 0.2f * e0;
        float w0 = __expf(e0);
        ssum += w0;
        acca.x = fmaf(w0, ha0.x, acca.x);
        acca.y = fmaf(w0, ha0.y, acca.y);
        acca.z = fmaf(w0, ha0.z, acca.z);
        acca.w = fmaf(w0, ha0.w, acca.w);
        accb.x = fmaf(w0, hb0.x, accb.x);
        accb.y = fmaf(w0, hb0.y, accb.y);
        accb.z = fmaf(w0, hb0.z, accb.z);
        accb.w = fmaf(w0, hb0.w, accb.w);
    }

    float inv = 1.f / (ssum + 1e-9f);
    float o[8] = {acca.x * inv, acca.y * inv, acca.z * inv, acca.w * inv,
                  accb.x * inv, accb.y * inv, accb.z * inv, accb.w * inv};
#pragma unroll
    for (int i = 0; i < 8; i++) o[i] = (o[i] > 0.f) ? o[i] : expm1f(o[i]);

    if (LAST) {
        const int dbase = (lane & 7) * 8;
        float s = 0.f;
#pragma unroll
        for (int i = 0; i < 8; i++) s += o[i] * Wout[dbase + i];
#pragma unroll
        for (int off = 16; off >= 1; off >>= 1) s += __shfl_xor_sync(0xffffffffu, s, off);
        if (lane == 0) {
            float r = 0.25f * s + bout[0];
            out[v] = (r > 0.f) ? r : 0.f;
        }
    } else {
        __nv_bfloat16 hi[8], lo[8];
#pragma unroll
        for (int i = 0; i < 8; i++) {
            hi[i] = __float2bfloat16(o[i]);
            lo[i] = __float2bfloat16(o[i] - __bfloat162float(hi[i]));
        }
        *(uint4*)(g_a_hi + (size_t)v * 256 + lane * 8) = *(const uint4*)hi;
        *(uint4*)(g_a_lo + (size_t)v * 256 + lane * 8) = *(const uint4*)lo;
    }
}

// ---------------- launch (two-stream fork/join, graph-capture safe) ----------------
extern "C" void kernel_launch(void* const* d_in, const int* in_sizes, int n_in,
                              void* d_out, int out_size) {
    const float* x    = (const float*)d_in[0];
    const int*   src  = (const int*)d_in[1];
    const int*   dst  = (const int*)d_in[2];
    const float* W0   = (const float*)d_in[3];
    const float* al0  = (const float*)d_in[4];
    const float* ar0  = (const float*)d_in[5];
    const float* W1   = (const float*)d_in[6];
    const float* al1  = (const float*)d_in[7];
    const float* ar1  = (const float*)d_in[8];
    const float* W2   = (const float*)d_in[9];
    const float* al2  = (const float*)d_in[10];
    const float* ar2  = (const float*)d_in[11];
    const float* Wout = (const float*)d_in[12];
    const float* bout = (const float*)d_in[13];

    const int N = N_NODES;
    const int E = N_EDGES;

    float *h;
    __nv_bfloat16 *ah, *al, *wh, *wl;
    cudaGetSymbolAddress((void**)&h, g_h);
    cudaGetSymbolAddress((void**)&ah, g_a_hi);
    cudaGetSymbolAddress((void**)&al, g_a_lo);
    cudaGetSymbolAddress((void**)&wh, g_w_hi);
    cudaGetSymbolAddress((void**)&wl, g_w_lo);

    // lazy one-time stream/event creation (first call is the uncaptured correctness run)
    static cudaStream_t s2 = nullptr;
    static cudaEvent_t e_fork = nullptr, e_join = nullptr;
    static bool smem_set = false;
    if (!s2) {
        cudaStreamCreateWithFlags(&s2, cudaStreamNonBlocking);
        cudaEventCreateWithFlags(&e_fork, cudaEventDisableTiming);
        cudaEventCreateWithFlags(&e_join, cudaEventDisableTiming);
    }
    if (!smem_set) {
        cudaFuncSetAttribute(gemm_db_k, cudaFuncAttributeMaxDynamicSharedMemorySize, DB_SMEM);
        smem_set = true;
    }

    dim3 ggrid(2, (N + 127) / 128);
    const int warpGrid = (N + 3) / 4;
    const int wtotal = 128 * 256 + 2 * 256 * 256;

    // ---- fork ----
    cudaEventRecord(e_fork, 0);
    cudaStreamWaitEvent(s2, e_fork, 0);

    // main stream: weight convert -> layer-0 GEMM (launch slots 0 and 3 -> gemm_l0 profiled)
    convert_w_all_k<<<(wtotal + 255) / 256, 256>>>(W0, W1, W2);
    // side stream: CSR build chain
    zero_counts_k<<<(N + 255) / 256, 256, 0, s2>>>();
    hist_k<<<(E + 255) / 256, 256, 0, s2>>>(dst, E);
    gemm_l0_k<<<ggrid, 256>>>(x, wh + 0 * 65536, wl + 0 * 65536, h, al0, ar0);
    partial_k<<<NBLK, 256, 0, s2>>>();
    scanpart_k<<<1, 256, 0, s2>>>();
    rowptr_k<<<NBLK, 256, 0, s2>>>();
    scatter_k<<<(E + 255) / 256, 256, 0, s2>>>(src, dst, E);

    // ---- join ----
    cudaEventRecord(e_join, s2);
    cudaStreamWaitEvent(0, e_join, 0);

    aggregate_k<false><<<warpGrid, 128>>>(h, nullptr, nullptr, nullptr, N);
    gemm_db_k<<<ggrid, 256, DB_SMEM>>>(ah, al, wh + 1 * 65536, wl + 1 * 65536, h, al1, ar1);
    aggregate_k<false><<<warpGrid, 128>>>(h, nullptr, nullptr, nullptr, N);
    gemm_db_k<<<ggrid, 256, DB_SMEM>>>(ah, al, wh + 2 * 65536, wl + 2 * 65536, h, al2, ar2);
    aggregate_k<true><<<warpGrid, 128>>>(h, (float*)d_out, Wout, bout, N);
}

// round 15
// speedup vs baseline: 1.2097x; 1.0858x over previous
#include <cuda_runtime.h>
#include <cuda_bf16.h>
#include <cuda_fp16.h>
#include <math.h>
#include <stdint.h>

#define N_NODES 50000
#define N_EDGES 800000
#define HH 256
#define NHEADS 4
#define MPAD 50048
#define NBLK 196          // ceil(N_NODES/256)

// ---------------- scratch ----------------
__device__ float  g_h  [(size_t)N_NODES * HH];   // layer-2 payload (fp32)
__device__ __half g_hf [(size_t)N_NODES * HH];   // layer-0/1 payload (fp16)
__device__ float g_el [N_NODES * NHEADS];
__device__ float g_er [N_NODES * NHEADS];
__device__ int   g_rowptr[N_NODES + 1];
__device__ int   g_counts[N_NODES];
__device__ int   g_csr_src[N_EDGES];
__device__ int   g_part[NBLK];
__device__ int   g_partoff[NBLK];
__device__ __nv_bfloat16 g_a_hi[(size_t)MPAD * 256];
__device__ __nv_bfloat16 g_a_lo[(size_t)MPAD * 256];
// weights in mma B-FRAGMENT order
__device__ __nv_bfloat16 g_w_hi[3 * 256 * 256];
__device__ __nv_bfloat16 g_w_lo[3 * 256 * 256];

// ---------------- weight conversion to fragment layout ----------------
__global__ void convert_w_all_k(const float* __restrict__ W0,
                                const float* __restrict__ W1,
                                const float* __restrict__ W2) {
    int i = blockIdx.x * blockDim.x + threadIdx.x;
    const float* W;
    __nv_bfloat16 *oh, *ol;
    int K, idx;
    if (i < 128 * 256) {
        W = W0; K = 128; idx = i;
        oh = g_w_hi + 0 * 65536; ol = g_w_lo + 0 * 65536;
    } else if (i < 128 * 256 + 256 * 256) {
        W = W1; K = 256; idx = i - 128 * 256;
        oh = g_w_hi + 1 * 65536; ol = g_w_lo + 1 * 65536;
    } else if (i < 128 * 256 + 2 * 256 * 256) {
        W = W2; K = 256; idx = i - 128 * 256 - 256 * 256;
        oh = g_w_hi + 2 * 65536; ol = g_w_lo + 2 * 65536;
    } else return;
    int k = idx / 256, n = idx % 256;
    float a = W[idx];
    __nv_bfloat16 hi = __float2bfloat16(a);
    __nv_bfloat16 lo = __float2bfloat16(a - __bfloat162float(hi));
    int nt = n >> 4, kt = k >> 4;
    int nn = n & 15, kq = k & 15;
    int m = ((kq >> 3) << 1) | (nn >> 3);
    int l = ((nn & 7) << 2) + ((kq & 7) >> 1);
    int off = (nt * (K >> 4) + kt) * 256 + l * 8 + m * 2 + (kq & 1);
    oh[off] = hi;
    ol[off] = lo;
}

// ---------------- CSR build ----------------
__global__ void zero_counts_k() {
    int i = blockIdx.x * blockDim.x + threadIdx.x;
    if (i < N_NODES) g_counts[i] = 0;
}
__global__ void hist_k(const int* __restrict__ dst, int E) {
    int i = blockIdx.x * blockDim.x + threadIdx.x;
    if (i < E) atomicAdd(&g_counts[dst[i]], 1);
}
__global__ void partial_k() {
    __shared__ int sh[256];
    int b = blockIdx.x, t = threadIdx.x;
    int i = b * 256 + t;
    sh[t] = (i < N_NODES) ? g_counts[i] : 0;
    __syncthreads();
#pragma unroll
    for (int off = 128; off >= 1; off >>= 1) {
        if (t < off) sh[t] += sh[t + off];
        __syncthreads();
    }
    if (t == 0) g_part[b] = sh[0];
}
__global__ void scanpart_k() {
    __shared__ int sh[256];
    int t = threadIdx.x;
    int v = (t < NBLK) ? g_part[t] : 0;
    sh[t] = v;
    __syncthreads();
#pragma unroll
    for (int off = 1; off < 256; off <<= 1) {
        int u = (t >= off) ? sh[t - off] : 0;
        __syncthreads();
        sh[t] += u;
        __syncthreads();
    }
    if (t < NBLK) g_partoff[t] = sh[t] - v;
    if (t == NBLK - 1) g_rowptr[N_NODES] = sh[t];
}
__global__ void rowptr_k() {
    __shared__ int sh[256];
    int b = blockIdx.x, t = threadIdx.x;
    int i = b * 256 + t;
    int v = (i < N_NODES) ? g_counts[i] : 0;
    sh[t] = v;
    __syncthreads();
#pragma unroll
    for (int off = 1; off < 256; off <<= 1) {
        int u = (t >= off) ? sh[t - off] : 0;
        __syncthreads();
        sh[t] += u;
        __syncthreads();
    }
    if (i < N_NODES) {
        g_rowptr[i] = g_partoff[b] + sh[t] - v;
        g_counts[i] = 0;
    }
}
__global__ void scatter_k(const int* __restrict__ src, const int* __restrict__ dst, int E) {
    int i = blockIdx.x * blockDim.x + threadIdx.x;
    if (i < E) {
        int d = dst[i];
        int pos = g_rowptr[d] + atomicAdd(&g_counts[d], 1);
        g_csr_src[pos] = src[i];
    }
}

// ---------------- warp-MMA helpers ----------------
__device__ __forceinline__ void ldsm4(uint32_t (&r)[4], uint32_t addr) {
    asm volatile("ldmatrix.sync.aligned.m8n8.x4.shared.b16 {%0,%1,%2,%3}, [%4];"
                 : "=r"(r[0]), "=r"(r[1]), "=r"(r[2]), "=r"(r[3]) : "r"(addr));
}
__device__ __forceinline__ void mma16816(float (&d)[4], const uint32_t (&a)[4],
                                         uint32_t b0, uint32_t b1) {
    asm volatile(
        "mma.sync.aligned.m16n8k16.row.col.f32.bf16.bf16.f32 "
        "{%0,%1,%2,%3}, {%4,%5,%6,%7}, {%8,%9}, {%0,%1,%2,%3};"
        : "+f"(d[0]), "+f"(d[1]), "+f"(d[2]), "+f"(d[3])
        : "r"(a[0]), "r"(a[1]), "r"(a[2]), "r"(a[3]), "r"(b0), "r"(b1));
}
__device__ __forceinline__ void cp16(uint32_t dst, const void* src, uint32_t n) {
    asm volatile("cp.async.cg.shared.global [%0], [%1], 16, %2;"
                 :: "r"(dst), "l"(src), "r"(n) : "memory");
}
#define CP_COMMIT() asm volatile("cp.async.commit_group;" ::: "memory")
#define CP_WAIT(n)  asm volatile("cp.async.wait_group %0;" :: "n"(n) : "memory")

#define LDA 80
#define ARR_BYTES (128 * LDA)
#define A_STAGE (2 * ARR_BYTES)
#define DB_SMEM (2 * A_STAGE)        // 40960

// ===== epilogue: write C (fp16 or fp32) + fused el/er =====
template <typename CT>
__device__ __forceinline__ void gemm_epilogue(
    float (&acc)[2][8][4], CT* __restrict__ C,
    const float* __restrict__ alw, const float* __restrict__ arw,
    int row0, int nbase, int warp_m, int warp_n, int lane)
{
    const int g = lane >> 2;
    const int tig = lane & 3;
    const int head = (nbase >> 6) + warp_n;
    const int cihb = tig * 2;
#pragma unroll
    for (int mt = 0; mt < 2; mt++) {
#pragma unroll
        for (int half = 0; half < 2; half++) {
            int grow = row0 + warp_m * 32 + mt * 16 + g + half * 8;
            if (grow >= N_NODES) continue;
            float sl = 0.f, sr = 0.f;
            CT* cp = C + (size_t)grow * 256 + nbase + warp_n * 64;
#pragma unroll
            for (int nt = 0; nt < 8; nt++) {
                float c0 = acc[mt][nt][half * 2 + 0];
                float c1 = acc[mt][nt][half * 2 + 1];
                int cih = nt * 8 + cihb;
                if (sizeof(CT) == 2) {
                    *(__half2*)((__half*)cp + cih) = __floats2half2_rn(c0, c1);
                } else {
                    *(float2*)((float*)cp + cih) = make_float2(c0, c1);
                }
                sl += c0 * alw[head * 64 + cih] + c1 * alw[head * 64 + cih + 1];
                sr += c0 * arw[head * 64 + cih] + c1 * arw[head * 64 + cih + 1];
            }
            sl += __shfl_xor_sync(0xffffffffu, sl, 1);
            sl += __shfl_xor_sync(0xffffffffu, sl, 2);
            sr += __shfl_xor_sync(0xffffffffu, sr, 1);
            sr += __shfl_xor_sync(0xffffffffu, sr, 2);
            if (tig == 0) {
                g_el[grow * 4 + head] = sl;
                g_er[grow * 4 + head] = sr;
            }
        }
    }
}

// ===== compute one staged 32-K chunk; B fragments from global =====
template <int KT>
__device__ __forceinline__ void gemm_chunk_compute_bd(
    float (&acc)[2][8][4], uint32_t uAh, uint32_t uAl, uint32_t aOff,
    const __nv_bfloat16* __restrict__ BhW,
    const __nv_bfloat16* __restrict__ BlW,
    int kt0, int lane)
{
#pragma unroll
    for (int kk = 0; kk < 2; kk++) {
        const uint32_t kb = kk * 32;
        const int kt = kt0 + kk;
        uint32_t aH[2][4];
#pragma unroll
        for (int mt = 0; mt < 2; mt++) ldsm4(aH[mt], uAh + aOff + mt * 16 * LDA + kb);
        {
            uint4 bH[4];
#pragma unroll
            for (int p = 0; p < 4; p++)
                bH[p] = ((const uint4*)(BhW + (size_t)(p * KT + kt) * 256))[lane];
#pragma unroll
            for (int mt = 0; mt < 2; mt++)
#pragma unroll
                for (int p = 0; p < 4; p++) {
                    mma16816(acc[mt][2 * p + 0], aH[mt], bH[p].x, bH[p].z);
                    mma16816(acc[mt][2 * p + 1], aH[mt], bH[p].y, bH[p].w);
                }
            uint32_t aL[2][4];
#pragma unroll
            for (int mt = 0; mt < 2; mt++) ldsm4(aL[mt], uAl + aOff + mt * 16 * LDA + kb);
#pragma unroll
            for (int mt = 0; mt < 2; mt++)
#pragma unroll
                for (int p = 0; p < 4; p++) {
                    mma16816(acc[mt][2 * p + 0], aL[mt], bH[p].x, bH[p].z);
                    mma16816(acc[mt][2 * p + 1], aL[mt], bH[p].y, bH[p].w);
                }
        }
        {
            uint4 bL[4];
#pragma unroll
            for (int p = 0; p < 4; p++)
                bL[p] = ((const uint4*)(BlW + (size_t)(p * KT + kt) * 256))[lane];
#pragma unroll
            for (int mt = 0; mt < 2; mt++)
#pragma unroll
                for (int p = 0; p < 4; p++) {
                    mma16816(acc[mt][2 * p + 0], aH[mt], bL[p].x, bL[p].z);
                    mma16816(acc[mt][2 * p + 1], aH[mt], bL[p].y, bL[p].w);
                }
        }
    }
}

// ---------------- layer-0 GEMM: fp32 A staged + split, B direct-frag, fp16 C ----------------
__global__ void __launch_bounds__(256, 2) gemm_l0_k(
    const float* __restrict__ Afp,
    const __nv_bfloat16* __restrict__ BhF, const __nv_bfloat16* __restrict__ BlF,
    __half* __restrict__ C, const float* __restrict__ alw, const float* __restrict__ arw)
{
    constexpr int K = 128, KT = K / 16;
    __shared__ __align__(16) uint8_t sAh[128 * LDA];
    __shared__ __align__(16) uint8_t sAl[128 * LDA];

    const int t = threadIdx.x;
    const int wid = t >> 5, lane = t & 31;
    const int warp_m = wid & 3, warp_n = wid >> 2;
    const int row0 = blockIdx.y * 128;
    const int nbase = blockIdx.x * 128;

    float acc[2][8][4];
#pragma unroll
    for (int i = 0; i < 2; i++)
#pragma unroll
        for (int j = 0; j < 8; j++)
#pragma unroll
            for (int q = 0; q < 4; q++) acc[i][j][q] = 0.f;

    const uint32_t uAh = (uint32_t)__cvta_generic_to_shared(sAh);
    const uint32_t uAl = (uint32_t)__cvta_generic_to_shared(sAl);
    const uint32_t rowOff = (uint32_t)(lane & 15) * LDA + (uint32_t)((lane >> 4) << 4);
    const uint32_t aOff = (uint32_t)warp_m * 32 * LDA + rowOff;
    const int ntb = (nbase >> 4) + warp_n * 4;
    const __nv_bfloat16* BhW = BhF + (size_t)ntb * KT * 256;
    const __nv_bfloat16* BlW = BlF + (size_t)ntb * KT * 256;

    const int lrow = t >> 1;
    const int lkq = (t & 1) * 16;
    const int arow = row0 + lrow;
    const bool aok = arow < N_NODES;

    for (int k0 = 0; k0 < K; k0 += 32) {
        {
            uint8_t* da = sAh + lrow * LDA + lkq * 2;
            uint8_t* dl = sAl + lrow * LDA + lkq * 2;
            const float* pa32 = Afp + (size_t)arow * K + k0 + lkq;
            float f[16];
#pragma unroll
            for (int q = 0; q < 4; q++) {
                float4 v = aok ? ((const float4*)pa32)[q] : make_float4(0.f, 0.f, 0.f, 0.f);
                f[q * 4 + 0] = v.x; f[q * 4 + 1] = v.y;
                f[q * 4 + 2] = v.z; f[q * 4 + 3] = v.w;
            }
            __nv_bfloat16 hi[16], lo[16];
#pragma unroll
            for (int q = 0; q < 16; q++) {
                hi[q] = __float2bfloat16(f[q]);
                lo[q] = __float2bfloat16(f[q] - __bfloat162float(hi[q]));
            }
            *(uint4*)(da +  0) = ((const uint4*)hi)[0];
            *(uint4*)(da + 16) = ((const uint4*)hi)[1];
            *(uint4*)(dl +  0) = ((const uint4*)lo)[0];
            *(uint4*)(dl + 16) = ((const uint4*)lo)[1];
        }
        __syncthreads();
        gemm_chunk_compute_bd<KT>(acc, uAh, uAl, aOff, BhW, BlW, k0 >> 4, lane);
        __syncthreads();
    }
    gemm_epilogue<__half>(acc, C, alw, arw, row0, nbase, warp_m, warp_n, lane);
}

// ---------------- layers 1-2 GEMM: bf16 A cp.async double buffer, B direct-frag ----------------
template <typename CT>
__global__ void __launch_bounds__(256, 2) gemm_db_k(
    const __nv_bfloat16* __restrict__ Ah, const __nv_bfloat16* __restrict__ Al,
    const __nv_bfloat16* __restrict__ BhF, const __nv_bfloat16* __restrict__ BlF,
    CT* __restrict__ C, const float* __restrict__ alw, const float* __restrict__ arw)
{
    constexpr int K = 256, KT = K / 16;
    constexpr int NCHUNK = K / 32;
    extern __shared__ __align__(16) uint8_t smem[];

    const int t = threadIdx.x;
    const int wid = t >> 5, lane = t & 31;
    const int warp_m = wid & 3, warp_n = wid >> 2;
    const int row0 = blockIdx.y * 128;
    const int nbase = blockIdx.x * 128;

    float acc[2][8][4];
#pragma unroll
    for (int i = 0; i < 2; i++)
#pragma unroll
        for (int j = 0; j < 8; j++)
#pragma unroll
            for (int q = 0; q < 4; q++) acc[i][j][q] = 0.f;

    const uint32_t sbase = (uint32_t)__cvta_generic_to_shared(smem);
    const uint32_t rowOff = (uint32_t)(lane & 15) * LDA + (uint32_t)((lane >> 4) << 4);
    const uint32_t aOff = (uint32_t)warp_m * 32 * LDA + rowOff;
    const int ntb = (nbase >> 4) + warp_n * 4;
    const __nv_bfloat16* BhW = BhF + (size_t)ntb * KT * 256;
    const __nv_bfloat16* BlW = BlF + (size_t)ntb * KT * 256;

    const int lrow = t >> 1;
    const int lhalf = (t & 1) * 32;
    const int arow_real = row0 + lrow;
    const bool aok = arow_real < N_NODES;
    const int arow = aok ? arow_real : (N_NODES - 1);
    const uint32_t asz = aok ? 16u : 0u;
    const uint32_t dOff = (uint32_t)lrow * LDA + (uint32_t)lhalf;

    auto issue = [&](int c, int stage) {
        const int k0 = c * 32;
        const uint32_t sb = sbase + stage * A_STAGE + dOff;
        const char* pa = (const char*)(Ah + (size_t)arow * K + k0) + lhalf;
        const char* pl = (const char*)(Al + (size_t)arow * K + k0) + lhalf;
        cp16(sb + 0 * ARR_BYTES +  0, pa +  0, asz);
        cp16(sb + 0 * ARR_BYTES + 16, pa + 16, asz);
        cp16(sb + 1 * ARR_BYTES +  0, pl +  0, asz);
        cp16(sb + 1 * ARR_BYTES + 16, pl + 16, asz);
        CP_COMMIT();
    };

    issue(0, 0);
    for (int c = 0; c < NCHUNK; c++) {
        const int stage = c & 1;
        if (c + 1 < NCHUNK) {
            issue(c + 1, stage ^ 1);
            CP_WAIT(1);
        } else {
            CP_WAIT(0);
        }
        __syncthreads();
        const uint32_t uAh = sbase + stage * A_STAGE;
        gemm_chunk_compute_bd<KT>(acc, uAh, uAh + ARR_BYTES, aOff, BhW, BlW, c * 2, lane);
        __syncthreads();
    }
    gemm_epilogue<CT>(acc, C, alw, arw, row0, nbase, warp_m, warp_n, lane);
}

// ---------------- single-pass aggregate ----------------
// LAST=false: payload fp16, emit bf16 hi/lo for next GEMM
// LAST=true:  payload fp32, fused final head
template <bool LAST>
__global__ void __launch_bounds__(128) aggregate_k(const __half* __restrict__ hf,
                                                   const float* __restrict__ h32,
                                                   float* __restrict__ out,
                                                   const float* __restrict__ Wout,
                                                   const float* __restrict__ bout, int N) {
    int v = (blockIdx.x * 128 + threadIdx.x) >> 5;
    int lane = threadIdx.x & 31;
    if (v >= N) return;
    int hd = lane >> 3;

    float4 er4 = ((const float4*)g_er)[v];
    float erv = (hd == 0) ? er4.x : (hd == 1) ? er4.y : (hd == 2) ? er4.z : er4.w;

    int r0 = g_rowptr[v];
    int r1 = g_rowptr[v + 1];

    float ssum = 0.f;
    float4 acca = make_float4(0.f, 0.f, 0.f, 0.f);
    float4 accb = make_float4(0.f, 0.f, 0.f, 0.f);

    auto edge_w = [&](int s) -> float {
        float4 el4 = ((const float4*)g_el)[s];
        float elv = (hd == 0) ? el4.x : (hd == 1) ? el4.y : (hd == 2) ? el4.z : el4.w;
        float e = elv + erv;
        e = (e > 0.f) ? e : 0.2f * e;
        return __expf(e);
    };

    int j = r0;
    for (; j + 2 <= r1; j += 2) {
        int s0 = g_csr_src[j];
        int s1 = g_csr_src[j + 1];
        float w0 = edge_w(s0);
        float w1 = edge_w(s1);
        float fa0[8], fa1[8];
        if (LAST) {
            const float4* hp0 = (const float4*)(h32 + (size_t)s0 * HH + lane * 8);
            const float4* hp1 = (const float4*)(h32 + (size_t)s1 * HH + lane * 8);
            float4 p0 = hp0[0], q0 = hp0[1], p1 = hp1[0], q1 = hp1[1];
            fa0[0]=p0.x; fa0[1]=p0.y; fa0[2]=p0.z; fa0[3]=p0.w;
            fa0[4]=q0.x; fa0[5]=q0.y; fa0[6]=q0.z; fa0[7]=q0.w;
            fa1[0]=p1.x; fa1[1]=p1.y; fa1[2]=p1.z; fa1[3]=p1.w;
            fa1[4]=q1.x; fa1[5]=q1.y; fa1[6]=q1.z; fa1[7]=q1.w;
        } else {
            uint4 hv0 = *(const uint4*)(hf + (size_t)s0 * HH + lane * 8);
            uint4 hv1 = *(const uint4*)(hf + (size_t)s1 * HH + lane * 8);
            const __half2* a0 = (const __half2*)&hv0;
            const __half2* a1 = (const __half2*)&hv1;
#pragma unroll
            for (int q = 0; q < 4; q++) {
                float2 f0 = __half22float2(a0[q]);
                float2 f1 = __half22float2(a1[q]);
                fa0[q * 2 + 0] = f0.x; fa0[q * 2 + 1] = f0.y;
                fa1[q * 2 + 0] = f1.x; fa1[q * 2 + 1] = f1.y;
            }
        }
        ssum += w0 + w1;
        acca.x = fmaf(w0, fa0[0], fmaf(w1, fa1[0], acca.x));
        acca.y = fmaf(w0, fa0[1], fmaf(w1, fa1[1], acca.y));
        acca.z = fmaf(w0, fa0[2], fmaf(w1, fa1[2], acca.z));
        acca.w = fmaf(w0, fa0[3], fmaf(w1, fa1[3], acca.w));
        accb.x = fmaf(w0, fa0[4], fmaf(w1, fa1[4], accb.x));
        accb.y = fmaf(w0, fa0[5], fmaf(w1, fa1[5], accb.y));
        accb.z = fmaf(w0, fa0[6], fmaf(w1, fa1[6], accb.z));
        accb.w = fmaf(w0, fa0[7], fmaf(w1, fa1[7], accb.w));
    }
    if (j < r1) {
        int s0 = g_csr_src[j];
        float w0 = edge_w(s0);
        float fa0[8];
        if (LAST) {
            const float4* hp0 = (const float4*)(h32 + (size_t)s0 * HH + lane * 8);
            float4 p0 = hp0[0], q0 = hp0[1];
            fa0[0]=p0.x; fa0[1]=p0.y; fa0[2]=p0.z; fa0[3]=p0.w;
            fa0[4]=q0.x; fa0[5]=q0.y; fa0[6]=q0.z; fa0[7]=q0.w;
        } else {
            uint4 hv0 = *(const uint4*)(hf + (size_t)s0 * HH + lane * 8);
            const __half2* a0 = (const __half2*)&hv0;
#pragma unroll
            for (int q = 0; q < 4; q++) {
                float2 f0 = __half22float2(a0[q]);
                fa0[q * 2 + 0] = f0.x; fa0[q * 2 + 1] = f0.y;
            }
        }
        ssum += w0;
        acca.x = fmaf(w0, fa0[0], acca.x);
        acca.y = fmaf(w0, fa0[1], acca.y);
        acca.z = fmaf(w0, fa0[2], acca.z);
        acca.w = fmaf(w0, fa0[3], acca.w);
        accb.x = fmaf(w0, fa0[4], accb.x);
        accb.y = fmaf(w0, fa0[5], accb.y);
        accb.z = fmaf(w0, fa0[6], accb.z);
        accb.w = fmaf(w0, fa0[7], accb.w);
    }

    float inv = 1.f / (ssum + 1e-9f);
    float o[8] = {acca.x * inv, acca.y * inv, acca.z * inv, acca.w * inv,
                  accb.x * inv, accb.y * inv, accb.z * inv, accb.w * inv};
#pragma unroll
    for (int i = 0; i < 8; i++) o[i] = (o[i] > 0.f) ? o[i] : expm1f(o[i]);

    if (LAST) {
        const int dbase = (lane & 7) * 8;
        float s = 0.f;
#pragma unroll
        for (int i = 0; i < 8; i++) s += o[i] * Wout[dbase + i];
#pragma unroll
        for (int off = 16; off >= 1; off >>= 1) s += __shfl_xor_sync(0xffffffffu, s, off);
        if (lane == 0) {
            float r = 0.25f * s + bout[0];
            out[v] = (r > 0.f) ? r : 0.f;
        }
    } else {
        __nv_bfloat16 hi[8], lo[8];
#pragma unroll
        for (int i = 0; i < 8; i++) {
            hi[i] = __float2bfloat16(o[i]);
            lo[i] = __float2bfloat16(o[i] - __bfloat162float(hi[i]));
        }
        *(uint4*)(g_a_hi + (size_t)v * 256 + lane * 8) = *(const uint4*)hi;
        *(uint4*)(g_a_lo + (size_t)v * 256 + lane * 8) = *(const uint4*)lo;
    }
}

// ---------------- launch (two-stream fork/join) ----------------
extern "C" void kernel_launch(void* const* d_in, const int* in_sizes, int n_in,
                              void* d_out, int out_size) {
    const float* x    = (const float*)d_in[0];
    const int*   src  = (const int*)d_in[1];
    const int*   dst  = (const int*)d_in[2];
    const float* W0   = (const float*)d_in[3];
    const float* al0  = (const float*)d_in[4];
    const float* ar0  = (const float*)d_in[5];
    const float* W1   = (const float*)d_in[6];
    const float* al1  = (const float*)d_in[7];
    const float* ar1  = (const float*)d_in[8];
    const float* W2   = (const float*)d_in[9];
    const float* al2  = (const float*)d_in[10];
    const float* ar2  = (const float*)d_in[11];
    const float* Wout = (const float*)d_in[12];
    const float* bout = (const float*)d_in[13];

    const int N = N_NODES;
    const int E = N_EDGES;

    float *h;
    __half *hf;
    __nv_bfloat16 *ah, *al, *wh, *wl;
    cudaGetSymbolAddress((void**)&h, g_h);
    cudaGetSymbolAddress((void**)&hf, g_hf);
    cudaGetSymbolAddress((void**)&ah, g_a_hi);
    cudaGetSymbolAddress((void**)&al, g_a_lo);
    cudaGetSymbolAddress((void**)&wh, g_w_hi);
    cudaGetSymbolAddress((void**)&wl, g_w_lo);

    static cudaStream_t s2 = nullptr;
    static cudaEvent_t e_fork = nullptr, e_join = nullptr;
    static bool smem_set = false;
    if (!s2) {
        cudaStreamCreateWithFlags(&s2, cudaStreamNonBlocking);
        cudaEventCreateWithFlags(&e_fork, cudaEventDisableTiming);
        cudaEventCreateWithFlags(&e_join, cudaEventDisableTiming);
    }
    if (!smem_set) {
        cudaFuncSetAttribute(gemm_db_k<__half>, cudaFuncAttributeMaxDynamicSharedMemorySize, DB_SMEM);
        cudaFuncSetAttribute(gemm_db_k<float>, cudaFuncAttributeMaxDynamicSharedMemorySize, DB_SMEM);
        smem_set = true;
    }

    dim3 ggrid(2, (N + 127) / 128);
    const int warpGrid = (N + 3) / 4;
    const int wtotal = 128 * 256 + 2 * 256 * 256;

    // ---- fork ----
    cudaEventRecord(e_fork, 0);
    cudaStreamWaitEvent(s2, e_fork, 0);

    convert_w_all_k<<<(wtotal + 255) / 256, 256>>>(W0, W1, W2);
    zero_counts_k<<<(N + 255) / 256, 256, 0, s2>>>();
    hist_k<<<(E + 255) / 256, 256, 0, s2>>>(dst, E);
    gemm_l0_k<<<ggrid, 256>>>(x, wh + 0 * 65536, wl + 0 * 65536, hf, al0, ar0);
    partial_k<<<NBLK, 256, 0, s2>>>();
    scanpart_k<<<1, 256, 0, s2>>>();
    rowptr_k<<<NBLK, 256, 0, s2>>>();
    scatter_k<<<(E + 255) / 256, 256, 0, s2>>>(src, dst, E);

    // ---- join ----
    cudaEventRecord(e_join, s2);
    cudaStreamWaitEvent(0, e_join, 0);

    aggregate_k<false><<<warpGrid, 128>>>(hf, nullptr, nullptr, nullptr, nullptr, N);
    gemm_db_k<__half><<<ggrid, 256, DB_SMEM>>>(ah, al, wh + 1 * 65536, wl + 1 * 65536, hf, al1, ar1);
    aggregate_k<false><<<warpGrid, 128>>>(hf, nullptr, nullptr, nullptr, nullptr, N);
    gemm_db_k<float><<<ggrid, 256, DB_SMEM>>>(ah, al, wh + 2 * 65536, wl + 2 * 65536, h, al2, ar2);
    aggregate_k<true><<<warpGrid, 128>>>(nullptr, h, (float*)d_out, Wout, bout, N);
}